// round 6
// baseline (speedup 1.0000x reference)
#include <cuda_runtime.h>
#include <cuda_bf16.h>

// B=262144, G=25, KIN=15, KOUT=3
// x:(B,375) f32  W:(25,3,15) f32  k_idx:(25,15) i32  v_idx:(25,3) i32  out:(B,75) f32
//
// Warp-per-group, lane-per-row. 25 warps (800 thr). Tile = 32 rows.
// sWI[g*15+i] = float4(bitcast(c), w0, w1, w2): one LDS.128 broadcast per i.
// x gather LDS: lane stride 375 (=23 mod 32) -> conflict-free, read-once.
// Double-buffered x staging overlaps compute; out goes through a smem
// transpose tile then coalesced float4 stores.

static constexpr int G     = 25;
static constexpr int KIN   = 15;
static constexpr int KOUT  = 3;
static constexpr int ROW_F = G * KIN;    // 375
static constexpr int OUT_F = G * KOUT;   // 75
static constexpr int ROWS  = 32;
static constexpr int NT    = 32 * G;     // 800 threads, warp w == group w
static constexpr int XF_TILE = ROWS * ROW_F;   // 12000 floats (48000 B)
static constexpr int X4_TILE = XF_TILE / 4;    // 3000 float4
static constexpr int OUTF_TILE = ROWS * OUT_F; // 2400 floats
static constexpr int O4_TILE   = OUTF_TILE / 4;// 600 float4
static constexpr int TBL = G * KIN;            // 375 float4 entries
// smem: sWI(375 f4) | sx0(12000 f) | sx1(12000 f) | sout(2400 f)
static constexpr size_t SMEM_BYTES =
    (size_t)(TBL * 4 + 2 * XF_TILE + OUTF_TILE) * sizeof(float);  // 111600

__global__ void __launch_bounds__(NT, 2)
mlp_rsna4_kernel(const float* __restrict__ x,
                 const float* __restrict__ W,
                 const int*   __restrict__ kidx,
                 const int*   __restrict__ vidx,
                 float*       __restrict__ out,
                 int B, int ntiles)
{
    extern __shared__ float4 smem4[];
    float4* sWI = smem4;                               // 375 float4
    float*  sx0 = reinterpret_cast<float*>(smem4 + TBL);
    float*  sx1 = sx0 + XF_TILE;
    float*  sout = sx1 + XF_TILE;
    float*  sxbuf[2] = { sx0, sx1 };

    const int tid = threadIdx.x;
    const int g   = tid >> 5;     // warp index = group
    const int ln  = tid & 31;     // lane = row within tile

    // Build packed (c, w0, w1, w2) table once per block.
    for (int t = tid; t < TBL; t += NT) {
        const int gg = t / KIN, ii = t % KIN;
        sWI[t] = make_float4(__int_as_float(kidx[t]),
                             W[(gg * KOUT + 0) * KIN + ii],
                             W[(gg * KOUT + 1) * KIN + ii],
                             W[(gg * KOUT + 2) * KIN + ii]);
    }
    // Warp-uniform scatter targets.
    const int vo0 = __ldg(&vidx[g * KOUT + 0]);
    const int vo1 = __ldg(&vidx[g * KOUT + 1]);
    const int vo2 = __ldg(&vidx[g * KOUT + 2]);

    // ---- staging helper ----
    auto stage = [&](int tile, int b) {
        const long long row0 = (long long)tile * ROWS;
        float* sb = sxbuf[b];
        if (row0 + ROWS <= (long long)B) {
            const float4* gx4 = reinterpret_cast<const float4*>(x + row0 * ROW_F);
            float4* sb4 = reinterpret_cast<float4*>(sb);
            #pragma unroll
            for (int k = 0; k < 4; k++) {
                int j = tid + k * NT;
                if (j < X4_TILE) sb4[j] = gx4[j];
            }
        } else {
            // tail tile (rare): scalar with zero fill
            const long long base = row0 * ROW_F;
            const long long lim  = (long long)B * ROW_F;
            for (int j = tid; j < XF_TILE; j += NT)
                sb[j] = (base + j < lim) ? x[base + j] : 0.f;
        }
    };

    int tile = blockIdx.x;
    if (tile < ntiles) stage(tile, 0);
    __syncthreads();

    int buf = 0;
    for (; tile < ntiles; tile += gridDim.x) {
        const int nxt = tile + gridDim.x;
        if (nxt < ntiles) stage(nxt, buf ^ 1);   // overlaps compute below

        // ---- compute: lane = row, all 3 outputs of group g ----
        const float* sb = sxbuf[buf] + ln * ROW_F;
        const float4* tw = sWI + g * KIN;
        float a0 = 0.f, a1 = 0.f, a2 = 0.f;
        #pragma unroll
        for (int i = 0; i < KIN; i++) {
            const float4 q = tw[i];               // LDS.128 broadcast
            const float xv = sb[__float_as_int(q.x)];  // conflict-free gather
            a0 = fmaf(xv, q.y, a0);
            a1 = fmaf(xv, q.z, a1);
            a2 = fmaf(xv, q.w, a2);
        }
        // transpose through smem (stride 75 = 11 mod 32: conflict-free)
        float* so = sout + ln * OUT_F;
        so[vo0] = a0; so[vo1] = a1; so[vo2] = a2;
        __syncthreads();

        // ---- coalesced float4 store of the out tile ----
        const long long row0 = (long long)tile * ROWS;
        if (tid < O4_TILE) {
            float4* go4 = reinterpret_cast<float4*>(out + row0 * OUT_F);
            if (row0 + ROWS <= (long long)B) {
                go4[tid] = reinterpret_cast<float4*>(sout)[tid];
            } else {
                const long long limf = ((long long)B - row0) * OUT_F;
                if (4 * tid + 3 < limf)
                    go4[tid] = reinterpret_cast<float4*>(sout)[tid];
                else {
                    for (int e = 0; e < 4; e++)
                        if (4 * tid + e < limf)
                            out[row0 * OUT_F + 4 * tid + e] = sout[4 * tid + e];
                }
            }
        }
        __syncthreads();   // staging done, sout free, buf free
        buf ^= 1;
    }
}

extern "C" void kernel_launch(void* const* d_in, const int* in_sizes, int n_in,
                              void* d_out, int out_size)
{
    const float* x    = (const float*)d_in[0];
    const float* W    = (const float*)d_in[1];
    const int*   kidx = (const int*)d_in[2];
    const int*   vidx = (const int*)d_in[3];
    float*       out  = (float*)d_out;

    const int B = in_sizes[0] / ROW_F;
    const int ntiles = (B + ROWS - 1) / ROWS;

    cudaFuncSetAttribute(mlp_rsna4_kernel,
                         cudaFuncAttributeMaxDynamicSharedMemorySize,
                         (int)SMEM_BYTES);

    int grid = 148 * 2;                 // persistent: 2 blocks/SM
    if (grid > ntiles) grid = ntiles;

    mlp_rsna4_kernel<<<grid, NT, SMEM_BYTES>>>(x, W, kidx, vidx, out, B, ntiles);
}